// round 1
// baseline (speedup 1.0000x reference)
#include <cuda_runtime.h>
#include <cstdint>

// ---------------- problem constants ----------------
#define NB    4
#define CIN1  512
#define COUT  256
#define HOUT  128          // spatial after upsample
#define NPIX  (HOUT*HOUT)  // 16384

// ---------------- scratch (device globals; no allocation allowed) ----------
__device__ float g_xumod[NB*CIN1*NPIX];      // upsampled & style-modulated input (134 MB)
__device__ float g_h1s2 [NB*COUT*NPIX];      // conv1 output, lrelu'd, pre-scaled by s2 (67 MB)
__device__ float g_w1p  [CIN1*(COUT/64)*576];
__device__ float g_w2p  [COUT*(COUT/64)*576];
__device__ float g_s1[NB*CIN1];
__device__ float g_s2[NB*COUT];
__device__ float g_s3[NB*COUT];
__device__ float g_d1[NB*COUT];
__device__ float g_d2[NB*COUT];
__device__ float g_w3m[NB*3*COUT];

// ---------------- style affine: s = w @ aW^T + aB ----------------
__global__ void style_kernel(const float* __restrict__ w,
                             const float* __restrict__ a1w, const float* __restrict__ a1b,
                             const float* __restrict__ a2w, const float* __restrict__ a2b,
                             const float* __restrict__ a3w, const float* __restrict__ a3b)
{
    int idx = blockIdx.x * blockDim.x + threadIdx.x;   // 0..4095
    const float* arow; const float* bias; float* out; int b, i;
    if (idx < 2048)      { b = idx >> 9;  i = idx & 511; arow = a1w + (size_t)i*512; bias = a1b; out = g_s1 + b*CIN1 + i; }
    else if (idx < 3072) { int t = idx - 2048; b = t >> 8; i = t & 255; arow = a2w + (size_t)i*512; bias = a2b; out = g_s2 + b*COUT + i; }
    else if (idx < 4096) { int t = idx - 3072; b = t >> 8; i = t & 255; arow = a3w + (size_t)i*512; bias = a3b; out = g_s3 + b*COUT + i; }
    else return;
    const float* wrow = w + (size_t)b*512;
    float acc = 0.f;
    #pragma unroll 8
    for (int k = 0; k < 512; ++k) acc = fmaf(wrow[k], arow[k], acc);
    *out = acc + bias[i];
}

// ---------------- demod factors: d[b,o] = rsqrt( sum_i s^2 * sum_k w^2 + eps )
__global__ void demod_kernel(const float* __restrict__ wgt, int CIN, int which)
{
    const float* s = which ? g_s2 : g_s1;
    float*       d = which ? g_d2 : g_d1;
    int o = blockIdx.x;               // 0..255
    int tid = threadIdx.x;            // 256 threads
    float pb[NB] = {0.f, 0.f, 0.f, 0.f};
    for (int i = tid; i < CIN; i += 256) {
        const float* wp = wgt + (size_t)(o*CIN + i)*9;
        float r = 0.f;
        #pragma unroll
        for (int t = 0; t < 9; ++t) { float v = wp[t]; r = fmaf(v, v, r); }
        #pragma unroll
        for (int b = 0; b < NB; ++b) { float sv = s[b*CIN + i]; pb[b] = fmaf(r, sv*sv, pb[b]); }
    }
    __shared__ float red[256];
    for (int b = 0; b < NB; ++b) {
        red[tid] = pb[b];
        __syncthreads();
        for (int st = 128; st > 0; st >>= 1) {
            if (tid < st) red[tid] += red[tid + st];
            __syncthreads();
        }
        if (tid == 0) d[b*COUT + o] = rsqrtf(red[0] + 1e-8f);
        __syncthreads();
    }
}

// ---------------- fold s3 into w3: w3m[b,c,o] = w3[c,o] * s3[b,o] ----------
__global__ void w3m_kernel(const float* __restrict__ w3)
{
    int idx = blockIdx.x * blockDim.x + threadIdx.x;
    if (idx >= NB*3*COUT) return;
    int o = idx & 255;
    int c = (idx >> 8) % 3;
    int b = idx / 768;
    g_w3m[idx] = w3[c*COUT + o] * g_s3[b*COUT + o];
}

// ---------------- weight repack: [o][ci][9] -> [ci][ocb][oi*9+tap] ---------
__global__ void repack_kernel(const float* __restrict__ w, float* __restrict__ wp,
                              int CIN, int OC)
{
    int idx = blockIdx.x * blockDim.x + threadIdx.x;
    if (idx >= OC*CIN*9) return;
    int tap = idx % 9;
    int t   = idx / 9;
    int ci  = t % CIN;
    int o   = t / CIN;
    int ocb = o >> 6, oi = o & 63;
    wp[(size_t)(ci*(OC >> 6) + ocb)*576 + oi*9 + tap] = w[idx];
}

// ---------------- bilinear x2 upsample (half-pixel) + s1 modulation --------
__global__ void upsample_kernel(const float* __restrict__ x)
{
    int idx = blockIdx.x * blockDim.x + threadIdx.x;    // 2^25 total
    int X  = idx & 127;
    int Y  = (idx >> 7) & 127;
    int ci = (idx >> 14) & 511;
    int b  = idx >> 23;
    int jy = Y >> 1, jx = X >> 1;
    int ya = jy + ((Y & 1) ? 0 : -1);
    float wya = (Y & 1) ? 0.75f : 0.25f;
    int yb = ya + 1; float wyb = 1.f - wya;
    int xa = jx + ((X & 1) ? 0 : -1);
    float wxa = (X & 1) ? 0.75f : 0.25f;
    int xb = xa + 1; float wxb = 1.f - wxa;
    ya = max(ya, 0); yb = min(yb, 63);
    xa = max(xa, 0); xb = min(xb, 63);
    const float* src = x + ((size_t)(b*CIN1 + ci) << 12);   // 64*64
    float v = wya * (wxa*src[ya*64 + xa] + wxb*src[ya*64 + xb])
            + wyb * (wxa*src[yb*64 + xa] + wxb*src[yb*64 + xb]);
    g_xumod[idx] = v * g_s1[b*CIN1 + ci];
}

// ---------------- main 3x3 conv (shared weights, per-(b,o) demod epilogue) -
// block: (tile 16x16 px, 64 oc, batch). 256 thr, 8oc x 8px micro-tile/thread.
template<int CIN, bool POST>
__global__ __launch_bounds__(256, 2)
void conv3x3_kernel(const float* __restrict__ in,    // [B,CIN,128,128]
                    const float* __restrict__ wp,    // repacked [ci][ocb][576]
                    const float* __restrict__ bias,  // [OC]
                    const float* __restrict__ demod, // [B,OC]
                    const float* __restrict__ post,  // [B,OC] or unused
                    float* __restrict__ out,         // [B,OC,128,128]
                    int OC)
{
    __shared__ __align__(16) float sIn[2][18*19];
    __shared__ __align__(16) float sW [2][576];

    const int tid    = threadIdx.x;
    const int tileId = blockIdx.x;            // 0..63
    const int ocb    = blockIdx.y;
    const int b      = blockIdx.z;
    const int baseY  = (tileId >> 3) << 4;
    const int baseX  = (tileId & 7) << 4;
    const int ocBase = ocb << 6;
    const int nOcb   = OC >> 6;

    const int lane = tid & 31;
    const int warp = tid >> 5;                // oc group (8 ocs)
    const int row  = lane >> 1;               // 0..15
    const int x0   = (lane & 1) << 3;         // 0 or 8

    float acc[8][8];
    #pragma unroll
    for (int i = 0; i < 8; ++i)
        #pragma unroll
        for (int j = 0; j < 8; ++j) acc[i][j] = 0.f;

    auto loadStage = [&](int ci, int p) {
        const float* inBase = in + ((size_t)(b*CIN + ci) << 14);
        #pragma unroll
        for (int t = tid; t < 324; t += 256) {
            int r = t / 18, c = t % 18;
            int gy = baseY + r - 1, gx = baseX + c - 1;
            uint32_t sa = (uint32_t)__cvta_generic_to_shared(&sIn[p][r*19 + c]);
            if ((unsigned)gy < 128u && (unsigned)gx < 128u) {
                asm volatile("cp.async.ca.shared.global [%0], [%1], 4;\n"
                             :: "r"(sa), "l"(inBase + (gy << 7) + gx));
            } else {
                sIn[p][r*19 + c] = 0.f;
            }
        }
        if (tid < 144) {
            const float* g = wp + (size_t)(ci*nOcb + ocb)*576 + tid*4;
            uint32_t sa = (uint32_t)__cvta_generic_to_shared(&sW[p][tid*4]);
            asm volatile("cp.async.cg.shared.global [%0], [%1], 16;\n"
                         :: "r"(sa), "l"(g));
        }
        asm volatile("cp.async.commit_group;\n");
    };

    loadStage(0, 0);

    for (int ci = 0; ci < CIN; ++ci) {
        int p = ci & 1;
        asm volatile("cp.async.wait_group 0;\n" ::: "memory");
        __syncthreads();
        if (ci + 1 < CIN) loadStage(ci + 1, p ^ 1);

        #pragma unroll
        for (int kh = 0; kh < 3; ++kh) {
            #pragma unroll
            for (int kw = 0; kw < 3; ++kw) {
                float wv[8];
                #pragma unroll
                for (int i = 0; i < 8; ++i)
                    wv[i] = sW[p][(warp*8 + i)*9 + kh*3 + kw];
                #pragma unroll
                for (int j = 0; j < 8; ++j) {
                    float xv = sIn[p][(row + kh)*19 + x0 + kw + j];
                    #pragma unroll
                    for (int i = 0; i < 8; ++i)
                        acc[i][j] = fmaf(wv[i], xv, acc[i][j]);
                }
            }
        }
    }

    // epilogue: demod, bias, leaky-relu, optional post-scale (s2 for conv1)
    #pragma unroll
    for (int i = 0; i < 8; ++i) {
        int o = ocBase + warp*8 + i;
        float d  = demod[b*OC + o];
        float bs = bias[o];
        float ps = POST ? post[b*OC + o] : 1.f;
        float* op = out + ((size_t)(b*OC + o) << 14) + ((baseY + row) << 7) + baseX + x0;
        float v[8];
        #pragma unroll
        for (int j = 0; j < 8; ++j) {
            float t = fmaf(acc[i][j], d, bs);
            t = t > 0.f ? t : 0.2f*t;
            v[j] = POST ? t*ps : t;
        }
        *(float4*)(op)     = make_float4(v[0], v[1], v[2], v[3]);
        *(float4*)(op + 4) = make_float4(v[4], v[5], v[6], v[7]);
    }
}

// ---------------- to_rgb: 1x1 conv over 256 ch, no demod, + bias, lrelu ----
__global__ void rgb_kernel(const float* __restrict__ h,   // [B,256,128,128]
                           const float* __restrict__ b3,
                           float* __restrict__ rgb)       // [B,3,128,128]
{
    int idx = blockIdx.x * blockDim.x + threadIdx.x;      // 0..65535
    int pix = idx & (NPIX - 1);
    int b   = idx >> 14;
    const float* hp = h + ((size_t)b * COUT << 14) + pix;
    const float* wm = g_w3m + b*3*COUT;
    float a0 = 0.f, a1 = 0.f, a2 = 0.f;
    #pragma unroll 4
    for (int o = 0; o < COUT; ++o) {
        float hv = hp[(size_t)o << 14];
        a0 = fmaf(hv, wm[o],            a0);
        a1 = fmaf(hv, wm[COUT + o],     a1);
        a2 = fmaf(hv, wm[2*COUT + o],   a2);
    }
    a0 += b3[0]; a1 += b3[1]; a2 += b3[2];
    a0 = a0 > 0.f ? a0 : 0.2f*a0;
    a1 = a1 > 0.f ? a1 : 0.2f*a1;
    a2 = a2 > 0.f ? a2 : 0.2f*a2;
    rgb[((size_t)(b*3 + 0) << 14) + pix] = a0;
    rgb[((size_t)(b*3 + 1) << 14) + pix] = a1;
    rgb[((size_t)(b*3 + 2) << 14) + pix] = a2;
}

// ---------------- launch ----------------
extern "C" void kernel_launch(void* const* d_in, const int* in_sizes, int n_in,
                              void* d_out, int out_size)
{
    const float* x   = (const float*)d_in[0];
    const float* w   = (const float*)d_in[1];
    const float* w1  = (const float*)d_in[2];
    const float* b1  = (const float*)d_in[3];
    const float* a1w = (const float*)d_in[4];
    const float* a1b = (const float*)d_in[5];
    const float* w2  = (const float*)d_in[6];
    const float* b2  = (const float*)d_in[7];
    const float* a2w = (const float*)d_in[8];
    const float* a2b = (const float*)d_in[9];
    const float* w3  = (const float*)d_in[10];
    const float* b3  = (const float*)d_in[11];
    const float* a3w = (const float*)d_in[12];
    const float* a3b = (const float*)d_in[13];

    float* out_h   = (float*)d_out;                       // [4,256,128,128]
    float* out_rgb = out_h + (size_t)NB*COUT*NPIX;        // [4,3,128,128]

    float *p_xumod, *p_h1s2, *p_w1p, *p_w2p, *p_s2, *p_d1, *p_d2;
    cudaGetSymbolAddress((void**)&p_xumod, g_xumod);
    cudaGetSymbolAddress((void**)&p_h1s2,  g_h1s2);
    cudaGetSymbolAddress((void**)&p_w1p,   g_w1p);
    cudaGetSymbolAddress((void**)&p_w2p,   g_w2p);
    cudaGetSymbolAddress((void**)&p_s2,    g_s2);
    cudaGetSymbolAddress((void**)&p_d1,    g_d1);
    cudaGetSymbolAddress((void**)&p_d2,    g_d2);

    // styles + weight prep (tiny)
    style_kernel<<<16, 256>>>(w, a1w, a1b, a2w, a2b, a3w, a3b);
    demod_kernel<<<COUT, 256>>>(w1, CIN1, 0);
    demod_kernel<<<COUT, 256>>>(w2, COUT, 1);
    w3m_kernel<<<12, 256>>>(w3);
    repack_kernel<<<(CIN1*COUT*9 + 255)/256, 256>>>(w1, p_w1p, CIN1, COUT);
    repack_kernel<<<(COUT*COUT*9 + 255)/256, 256>>>(w2, p_w2p, COUT, COUT);

    // upsample + modulate
    upsample_kernel<<<(NB*CIN1*NPIX)/256, 256>>>(x);

    // conv1: 512 -> 256, demod d1, +b1, lrelu, * s2  -> g_h1s2
    {
        dim3 grid(64, COUT/64, NB);
        conv3x3_kernel<CIN1, true><<<grid, 256>>>(p_xumod, p_w1p, b1, p_d1, p_s2, p_h1s2, COUT);
    }
    // conv2: 256 -> 256, demod d2, +b2, lrelu -> h output
    {
        dim3 grid(64, COUT/64, NB);
        conv3x3_kernel<COUT, false><<<grid, 256>>>(p_h1s2, p_w2p, b2, p_d2, nullptr, out_h, COUT);
    }
    // to_rgb
    rgb_kernel<<<(NB*NPIX)/256, 256>>>(out_h, b3, out_rgb);
}